// round 2
// baseline (speedup 1.0000x reference)
#include <cuda_runtime.h>

#define N   128
#define N2  (128 * 128)
#define N3  (128 * 128 * 128)

// Scratch (no allocations allowed)
__device__ float g_warped[N3];
__device__ float g_u[3 * N3];
__device__ float g_t[3 * N3];

// Gaussian weights sigma=1, radius=3, normalized (exp(-x^2/2)/sum)
__constant__ float GW[4] = {0.39905027f, 0.24203622f, 0.05400558f, 0.00443305f};

__global__ void zero_kernel(float* __restrict__ vf) {
    int i = blockIdx.x * blockDim.x + threadIdx.x;
    if (i < 3 * N3) vf[i] = 0.0f;
}

// Trilinear warp of moving image by displacement vf (3 channels, voxel units).
// map_coordinates(order=1, mode='nearest') == clamp coordinate to [0, N-1].
__global__ void warp_kernel(const float* __restrict__ moving,
                            const float* __restrict__ vf,
                            float* __restrict__ warped) {
    int i = blockIdx.x * blockDim.x + threadIdx.x;
    if (i >= N3) return;
    int w = i & 127;
    int h = (i >> 7) & 127;
    int d = i >> 14;

    float cd = (float)d + vf[i];
    float ch = (float)h + vf[i + N3];
    float cw = (float)w + vf[i + 2 * N3];
    cd = fminf(fmaxf(cd, 0.0f), 127.0f);
    ch = fminf(fmaxf(ch, 0.0f), 127.0f);
    cw = fminf(fmaxf(cw, 0.0f), 127.0f);

    int d0 = (int)cd, h0 = (int)ch, w0 = (int)cw;
    float fd = cd - (float)d0, fh = ch - (float)h0, fw = cw - (float)w0;
    int d1 = min(d0 + 1, 127), h1 = min(h0 + 1, 127), w1 = min(w0 + 1, 127);

    const float* p00 = moving + (d0 << 14);
    const float* p01 = moving + (d1 << 14);
    int r00 = (h0 << 7), r01 = (h1 << 7);

    float v000 = p00[r00 + w0], v001 = p00[r00 + w1];
    float v010 = p00[r01 + w0], v011 = p00[r01 + w1];
    float v100 = p01[r00 + w0], v101 = p01[r00 + w1];
    float v110 = p01[r01 + w0], v111 = p01[r01 + w1];

    float c00 = v000 + fw * (v001 - v000);
    float c01 = v010 + fw * (v011 - v010);
    float c10 = v100 + fw * (v101 - v100);
    float c11 = v110 + fw * (v111 - v110);
    float c0 = c00 + fh * (c01 - c00);
    float c1 = c10 + fh * (c11 - c10);
    warped[i] = c0 + fd * (c1 - c0);
}

// jnp.gradient semantics: one-sided at edges, central (0.5*(f[i+1]-f[i-1])) inside.
__device__ __forceinline__ float grad1(const float* __restrict__ a, int i, int c, int stride) {
    if (c == 0)   return a[i + stride] - a[i];
    if (c == 127) return a[i] - a[i - stride];
    return 0.5f * (a[i + stride] - a[i - stride]);
}

// Demon forces (dual) + u = vf + TAU * f  (TAU = 1)
__global__ void force_kernel(const float* __restrict__ warped,
                             const float* __restrict__ fixedi,
                             const float* __restrict__ vf,
                             float* __restrict__ u) {
    int i = blockIdx.x * blockDim.x + threadIdx.x;
    if (i >= N3) return;
    int w = i & 127;
    int h = (i >> 7) & 127;
    int d = i >> 14;

    float diff = warped[i] - fixedi[i];

    float g0 = 0.5f * (grad1(warped, i, d, N2)  + grad1(fixedi, i, d, N2));
    float g1 = 0.5f * (grad1(warped, i, h, N)   + grad1(fixedi, i, h, N));
    float g2 = 0.5f * (grad1(warped, i, w, 1)   + grad1(fixedi, i, w, 1));

    float denom = g0 * g0 + g1 * g1 + g2 * g2 + diff * diff;
    float s = (denom > 1e-6f) ? (diff / denom) : 0.0f;

    u[i]          = vf[i]          + s * g0;
    u[i + N3]     = vf[i + N3]     + s * g1;
    u[i + 2 * N3] = vf[i + 2 * N3] + s * g2;
}

// Separable 7-tap Gaussian along one axis, zero padding ('same' conv).
// STRIDE: 1 (w axis), 128 (h axis), 16384 (d axis).
template <int STRIDE>
__global__ void smooth_kernel(const float* __restrict__ in, float* __restrict__ out) {
    int i = blockIdx.x * blockDim.x + threadIdx.x;
    if (i >= 3 * N3) return;
    int vi = i & (N3 - 1);              // voxel index within channel
    int c = (vi / STRIDE) & 127;        // coordinate along the smoothing axis

    float acc = GW[0] * in[i];
#pragma unroll
    for (int t = 1; t <= 3; t++) {
        if (c - t >= 0)  acc += GW[t] * in[i - t * STRIDE];
        if (c + t <= 127) acc += GW[t] * in[i + t * STRIDE];
    }
    out[i] = acc;
}

extern "C" void kernel_launch(void* const* d_in, const int* in_sizes, int n_in,
                              void* d_out, int out_size) {
    const float* moving = (const float*)d_in[0];
    const float* fixedi = (const float*)d_in[1];
    float* vf = (float*)d_out;

    float *warped_p, *u_p, *t_p;
    cudaGetSymbolAddress((void**)&warped_p, g_warped);
    cudaGetSymbolAddress((void**)&u_p, g_u);
    cudaGetSymbolAddress((void**)&t_p, g_t);

    const int T = 256;
    const int B1 = N3 / T;          // 8192
    const int B3 = 3 * N3 / T;      // 24576

    zero_kernel<<<B3, T>>>(vf);

    for (int it = 0; it < 20; it++) {
        warp_kernel<<<B1, T>>>(moving, vf, warped_p);
        force_kernel<<<B1, T>>>(warped_p, fixedi, vf, u_p);
        smooth_kernel<N2><<<B3, T>>>(u_p, t_p);   // D axis
        smooth_kernel<N><<<B3, T>>>(t_p, u_p);    // H axis
        smooth_kernel<1><<<B3, T>>>(u_p, vf);     // W axis
    }
}

// round 3
// speedup vs baseline: 2.2384x; 2.2384x over previous
#include <cuda_runtime.h>

#define N   128
#define N2  (128 * 128)
#define N3  (128 * 128 * 128)

// Scratch (no allocations allowed)
__device__ float g_warped[N3];
__device__ float g_u[3 * N3];
__device__ float g_t[3 * N3];

// Gaussian weights sigma=1, radius=3, normalized
__constant__ float GW[4] = {0.39905027f, 0.24203622f, 0.05400558f, 0.00443305f};

__global__ void zero_kernel(float4* __restrict__ vf) {
    int i = blockIdx.x * blockDim.x + threadIdx.x;
    if (i < 3 * N3 / 4) vf[i] = make_float4(0.f, 0.f, 0.f, 0.f);
}

// ---------------------------------------------------------------------------
// Trilinear warp: each thread handles 4 consecutive-w voxels.
// map_coordinates(order=1, mode='nearest') == clamp coordinate to [0, N-1].
// ---------------------------------------------------------------------------
__device__ __forceinline__ float trilerp(const float* __restrict__ m,
                                         float cd, float ch, float cw) {
    cd = fminf(fmaxf(cd, 0.0f), 127.0f);
    ch = fminf(fmaxf(ch, 0.0f), 127.0f);
    cw = fminf(fmaxf(cw, 0.0f), 127.0f);
    int d0 = (int)cd, h0 = (int)ch, w0 = (int)cw;
    float fd = cd - (float)d0, fh = ch - (float)h0, fw = cw - (float)w0;
    int d1 = min(d0 + 1, 127), h1 = min(h0 + 1, 127), w1 = min(w0 + 1, 127);

    const float* p0 = m + (d0 << 14);
    const float* p1 = m + (d1 << 14);
    int r0 = (h0 << 7), r1 = (h1 << 7);

    float v000 = p0[r0 + w0], v001 = p0[r0 + w1];
    float v010 = p0[r1 + w0], v011 = p0[r1 + w1];
    float v100 = p1[r0 + w0], v101 = p1[r0 + w1];
    float v110 = p1[r1 + w0], v111 = p1[r1 + w1];

    float c00 = v000 + fw * (v001 - v000);
    float c01 = v010 + fw * (v011 - v010);
    float c10 = v100 + fw * (v101 - v100);
    float c11 = v110 + fw * (v111 - v110);
    float c0 = c00 + fh * (c01 - c00);
    float c1 = c10 + fh * (c11 - c10);
    return c0 + fd * (c1 - c0);
}

__global__ void warp_kernel(const float* __restrict__ moving,
                            const float4* __restrict__ vf4,
                            float4* __restrict__ warped4) {
    int i4 = blockIdx.x * blockDim.x + threadIdx.x;   // over N3/4
    if (i4 >= N3 / 4) return;
    int i = i4 * 4;
    int w = i & 127;
    int h = (i >> 7) & 127;
    int d = i >> 14;

    float4 vd = vf4[i4];
    float4 vh = vf4[i4 + N3 / 4];
    float4 vw = vf4[i4 + 2 * N3 / 4];

    float4 out;
    out.x = trilerp(moving, (float)d + vd.x, (float)h + vh.x, (float)(w + 0) + vw.x);
    out.y = trilerp(moving, (float)d + vd.y, (float)h + vh.y, (float)(w + 1) + vw.y);
    out.z = trilerp(moving, (float)d + vd.z, (float)h + vh.z, (float)(w + 2) + vw.z);
    out.w = trilerp(moving, (float)d + vd.w, (float)h + vh.w, (float)(w + 3) + vw.w);
    warped4[i4] = out;
}

// ---------------------------------------------------------------------------
// Demon forces (dual) + u = vf + TAU * f   (TAU = 1), float4 per thread.
// jnp.gradient: one-sided at edges, central elsewhere.
// ---------------------------------------------------------------------------
__device__ __forceinline__ float4 grad_s(const float4* __restrict__ a4,
                                         int i4, int c, int s4) {
    // gradient along a strided axis (d or h): whole float4 shares coordinate c
    float4 p, m;
    if (c == 0) {
        p = a4[i4 + s4]; m = a4[i4];
        return make_float4(p.x - m.x, p.y - m.y, p.z - m.z, p.w - m.w);
    }
    if (c == 127) {
        p = a4[i4]; m = a4[i4 - s4];
        return make_float4(p.x - m.x, p.y - m.y, p.z - m.z, p.w - m.w);
    }
    p = a4[i4 + s4]; m = a4[i4 - s4];
    return make_float4(0.5f * (p.x - m.x), 0.5f * (p.y - m.y),
                       0.5f * (p.z - m.z), 0.5f * (p.w - m.w));
}

__device__ __forceinline__ float4 grad_w(const float4* __restrict__ a4,
                                         int i4, int w0, float4 c) {
    float4 l = (w0 >= 4)   ? a4[i4 - 1] : make_float4(0.f, 0.f, 0.f, 0.f);
    float4 r = (w0 <= 120) ? a4[i4 + 1] : make_float4(0.f, 0.f, 0.f, 0.f);
    // a[w0-1 .. w0+4] = { l.w, c.x, c.y, c.z, c.w, r.x }
    float4 g;
    g.x = (w0 == 0)   ? (c.y - c.x) : 0.5f * (c.y - l.w);
    g.y = 0.5f * (c.z - c.x);
    g.z = 0.5f * (c.w - c.y);
    g.w = (w0 == 124) ? (c.w - c.z) : 0.5f * (r.x - c.z);
    return g;
}

__global__ void force_kernel(const float4* __restrict__ warped4,
                             const float4* __restrict__ fixed4,
                             const float4* __restrict__ vf4,
                             float4* __restrict__ u4) {
    int i4 = blockIdx.x * blockDim.x + threadIdx.x;   // over N3/4
    if (i4 >= N3 / 4) return;
    int i = i4 * 4;
    int w0 = i & 127;
    int h = (i >> 7) & 127;
    int d = i >> 14;

    float4 wc = warped4[i4];
    float4 fc = fixed4[i4];

    float4 gdw = grad_s(warped4, i4, d, N2 / 4);
    float4 gdf = grad_s(fixed4,  i4, d, N2 / 4);
    float4 ghw = grad_s(warped4, i4, h, N / 4);
    float4 ghf = grad_s(fixed4,  i4, h, N / 4);
    float4 gww = grad_w(warped4, i4, w0, wc);
    float4 gwf = grad_w(fixed4,  i4, w0, fc);

    float4 v0 = vf4[i4];
    float4 v1 = vf4[i4 + N3 / 4];
    float4 v2 = vf4[i4 + 2 * N3 / 4];

    float4 o0, o1, o2;
#pragma unroll
    for (int j = 0; j < 4; j++) {
        float diff = ((const float*)&wc)[j] - ((const float*)&fc)[j];
        float g0 = 0.5f * (((const float*)&gdw)[j] + ((const float*)&gdf)[j]);
        float g1 = 0.5f * (((const float*)&ghw)[j] + ((const float*)&ghf)[j]);
        float g2 = 0.5f * (((const float*)&gww)[j] + ((const float*)&gwf)[j]);
        float denom = g0 * g0 + g1 * g1 + g2 * g2 + diff * diff;
        float s = (denom > 1e-6f) ? (diff / denom) : 0.0f;
        ((float*)&o0)[j] = ((const float*)&v0)[j] + s * g0;
        ((float*)&o1)[j] = ((const float*)&v1)[j] + s * g1;
        ((float*)&o2)[j] = ((const float*)&v2)[j] + s * g2;
    }
    u4[i4]              = o0;
    u4[i4 + N3 / 4]     = o1;
    u4[i4 + 2 * N3 / 4] = o2;
}

// ---------------------------------------------------------------------------
// Separable 7-tap Gaussian, zero padding. Strided axes (d: S4=4096, h: S4=32).
// ---------------------------------------------------------------------------
template <int S4>
__global__ void smooth_s_kernel(const float4* __restrict__ in4,
                                float4* __restrict__ out4) {
    int i4 = blockIdx.x * blockDim.x + threadIdx.x;   // over 3*N3/4
    if (i4 >= 3 * N3 / 4) return;
    int vi = i4 & (N3 / 4 - 1);
    int c = (vi / S4) & 127;

    float4 x = in4[i4];
    float4 acc = make_float4(GW[0] * x.x, GW[0] * x.y, GW[0] * x.z, GW[0] * x.w);
#pragma unroll
    for (int t = 1; t <= 3; t++) {
        if (c - t >= 0) {
            float4 a = in4[i4 - t * S4];
            acc.x += GW[t] * a.x; acc.y += GW[t] * a.y;
            acc.z += GW[t] * a.z; acc.w += GW[t] * a.w;
        }
        if (c + t <= 127) {
            float4 a = in4[i4 + t * S4];
            acc.x += GW[t] * a.x; acc.y += GW[t] * a.y;
            acc.z += GW[t] * a.z; acc.w += GW[t] * a.w;
        }
    }
    out4[i4] = acc;
}

// W axis: 3 float4 loads give taps w0-4 .. w0+7; shift in registers.
__global__ void smooth_w_kernel(const float4* __restrict__ in4,
                                float4* __restrict__ out4) {
    int i4 = blockIdx.x * blockDim.x + threadIdx.x;   // over 3*N3/4
    if (i4 >= 3 * N3 / 4) return;
    int w0 = (i4 * 4) & 127;

    float4 c = in4[i4];
    float4 l = (w0 >= 4)   ? in4[i4 - 1] : make_float4(0.f, 0.f, 0.f, 0.f);
    float4 r = (w0 <= 120) ? in4[i4 + 1] : make_float4(0.f, 0.f, 0.f, 0.f);

    // a[0..9] = in[w0-3 .. w0+6] (zero-padded)
    float a[10] = {l.y, l.z, l.w, c.x, c.y, c.z, c.w, r.x, r.y, r.z};

    float4 o;
#pragma unroll
    for (int j = 0; j < 4; j++) {
        float acc = GW[0] * a[3 + j];
#pragma unroll
        for (int t = 1; t <= 3; t++)
            acc += GW[t] * (a[3 + j - t] + a[3 + j + t]);
        ((float*)&o)[j] = acc;
    }
    out4[i4] = o;
}

extern "C" void kernel_launch(void* const* d_in, const int* in_sizes, int n_in,
                              void* d_out, int out_size) {
    const float* moving = (const float*)d_in[0];
    const float4* fixed4 = (const float4*)d_in[1];
    float* vf = (float*)d_out;
    float4* vf4 = (float4*)d_out;

    float *warped_p, *u_p, *t_p;
    cudaGetSymbolAddress((void**)&warped_p, g_warped);
    cudaGetSymbolAddress((void**)&u_p, g_u);
    cudaGetSymbolAddress((void**)&t_p, g_t);
    float4* warped4 = (float4*)warped_p;
    float4* u4 = (float4*)u_p;
    float4* t4 = (float4*)t_p;

    const int T = 256;
    const int B1 = (N3 / 4) / T;          // 2048
    const int B3 = (3 * N3 / 4) / T;      // 6144

    zero_kernel<<<B3, T>>>(vf4);

    for (int it = 0; it < 20; it++) {
        warp_kernel<<<B1, T>>>(moving, vf4, warped4);
        force_kernel<<<B1, T>>>(warped4, fixed4, vf4, u4);
        smooth_s_kernel<N2 / 4><<<B3, T>>>(u4, t4);   // D axis
        smooth_s_kernel<N / 4><<<B3, T>>>(t4, u4);    // H axis
        smooth_w_kernel<<<B3, T>>>(u4, vf4);          // W axis
    }
}

// round 4
// speedup vs baseline: 2.8530x; 1.2746x over previous
#include <cuda_runtime.h>

#define N   128
#define N2  (128 * 128)
#define N3  (128 * 128 * 128)

// Scratch (no allocations allowed)
__device__ float g_warped[N3];
__device__ float g_u[3 * N3];
__device__ float g_t[3 * N3];

// Gaussian weights sigma=1, radius=3, normalized
__constant__ float GW[4] = {0.39905027f, 0.24203622f, 0.05400558f, 0.00443305f};

__global__ void zero_kernel(float4* __restrict__ vf) {
    int i = blockIdx.x * blockDim.x + threadIdx.x;
    if (i < 3 * N3 / 4) vf[i] = make_float4(0.f, 0.f, 0.f, 0.f);
}

// ---------------------------------------------------------------------------
// Trilinear warp: each thread handles 4 consecutive-w voxels.
// map_coordinates(order=1, mode='nearest') == clamp coordinate to [0, N-1].
// ---------------------------------------------------------------------------
__device__ __forceinline__ float trilerp(const float* __restrict__ m,
                                         float cd, float ch, float cw) {
    cd = fminf(fmaxf(cd, 0.0f), 127.0f);
    ch = fminf(fmaxf(ch, 0.0f), 127.0f);
    cw = fminf(fmaxf(cw, 0.0f), 127.0f);
    int d0 = (int)cd, h0 = (int)ch, w0 = (int)cw;
    float fd = cd - (float)d0, fh = ch - (float)h0, fw = cw - (float)w0;
    int d1 = min(d0 + 1, 127), h1 = min(h0 + 1, 127), w1 = min(w0 + 1, 127);

    const float* p0 = m + (d0 << 14);
    const float* p1 = m + (d1 << 14);
    int r0 = (h0 << 7), r1 = (h1 << 7);

    float v000 = p0[r0 + w0], v001 = p0[r0 + w1];
    float v010 = p0[r1 + w0], v011 = p0[r1 + w1];
    float v100 = p1[r0 + w0], v101 = p1[r0 + w1];
    float v110 = p1[r1 + w0], v111 = p1[r1 + w1];

    float c00 = v000 + fw * (v001 - v000);
    float c01 = v010 + fw * (v011 - v010);
    float c10 = v100 + fw * (v101 - v100);
    float c11 = v110 + fw * (v111 - v110);
    float c0 = c00 + fh * (c01 - c00);
    float c1 = c10 + fh * (c11 - c10);
    return c0 + fd * (c1 - c0);
}

__global__ void warp_kernel(const float* __restrict__ moving,
                            const float4* __restrict__ vf4,
                            float4* __restrict__ warped4) {
    int i4 = blockIdx.x * blockDim.x + threadIdx.x;   // over N3/4
    if (i4 >= N3 / 4) return;
    int i = i4 * 4;
    int w = i & 127;
    int h = (i >> 7) & 127;
    int d = i >> 14;

    float4 vd = vf4[i4];
    float4 vh = vf4[i4 + N3 / 4];
    float4 vw = vf4[i4 + 2 * N3 / 4];

    float4 out;
    out.x = trilerp(moving, (float)d + vd.x, (float)h + vh.x, (float)(w + 0) + vw.x);
    out.y = trilerp(moving, (float)d + vd.y, (float)h + vh.y, (float)(w + 1) + vw.y);
    out.z = trilerp(moving, (float)d + vd.z, (float)h + vh.z, (float)(w + 2) + vw.z);
    out.w = trilerp(moving, (float)d + vd.w, (float)h + vh.w, (float)(w + 3) + vw.w);
    warped4[i4] = out;
}

// ---------------------------------------------------------------------------
// Demon forces (dual) + u = vf + f, then W-axis 7-tap smooth via warp shuffle.
// Lane l holds w = [4l, 4l+3]; a warp spans a full 128-wide row.
// ---------------------------------------------------------------------------
__device__ __forceinline__ float4 grad_s(const float4* __restrict__ a4,
                                         int i4, int c, int s4) {
    float4 p, m;
    if (c == 0) {
        p = a4[i4 + s4]; m = a4[i4];
        return make_float4(p.x - m.x, p.y - m.y, p.z - m.z, p.w - m.w);
    }
    if (c == 127) {
        p = a4[i4]; m = a4[i4 - s4];
        return make_float4(p.x - m.x, p.y - m.y, p.z - m.z, p.w - m.w);
    }
    p = a4[i4 + s4]; m = a4[i4 - s4];
    return make_float4(0.5f * (p.x - m.x), 0.5f * (p.y - m.y),
                       0.5f * (p.z - m.z), 0.5f * (p.w - m.w));
}

// Central-difference gradient along w using shuffles (one-sided at w=0,127).
__device__ __forceinline__ float4 grad_w_shfl(float4 c, int lane) {
    float lw = __shfl_up_sync(0xFFFFFFFFu, c.w, 1);    // value at w0-1
    float rx = __shfl_down_sync(0xFFFFFFFFu, c.x, 1);  // value at w0+4
    float4 g;
    g.x = (lane == 0)  ? (c.y - c.x) : 0.5f * (c.y - lw);
    g.y = 0.5f * (c.z - c.x);
    g.z = 0.5f * (c.w - c.y);
    g.w = (lane == 31) ? (c.w - c.z) : 0.5f * (rx - c.z);
    return g;
}

// 7-tap Gaussian along w (zero-padded) using shuffles.
__device__ __forceinline__ float4 wsmooth_shfl(float4 u, int lane) {
    float ly = __shfl_up_sync(0xFFFFFFFFu, u.y, 1);
    float lz = __shfl_up_sync(0xFFFFFFFFu, u.z, 1);
    float lw = __shfl_up_sync(0xFFFFFFFFu, u.w, 1);
    float rx = __shfl_down_sync(0xFFFFFFFFu, u.x, 1);
    float ry = __shfl_down_sync(0xFFFFFFFFu, u.y, 1);
    float rz = __shfl_down_sync(0xFFFFFFFFu, u.z, 1);
    if (lane == 0)  { ly = 0.f; lz = 0.f; lw = 0.f; }
    if (lane == 31) { rx = 0.f; ry = 0.f; rz = 0.f; }
    float a[10] = {ly, lz, lw, u.x, u.y, u.z, u.w, rx, ry, rz};
    float4 o;
#pragma unroll
    for (int j = 0; j < 4; j++) {
        float acc = GW[0] * a[3 + j];
#pragma unroll
        for (int t = 1; t <= 3; t++)
            acc += GW[t] * (a[3 + j - t] + a[3 + j + t]);
        ((float*)&o)[j] = acc;
    }
    return o;
}

__global__ void force_w_kernel(const float4* __restrict__ warped4,
                               const float4* __restrict__ fixed4,
                               const float4* __restrict__ vf4,
                               float4* __restrict__ u4) {
    int i4 = blockIdx.x * blockDim.x + threadIdx.x;   // over N3/4
    if (i4 >= N3 / 4) return;
    int i = i4 * 4;
    int h = (i >> 7) & 127;
    int d = i >> 14;
    int lane = threadIdx.x & 31;   // == w4 index within the row

    float4 wc = warped4[i4];
    float4 fc = fixed4[i4];

    float4 gdw = grad_s(warped4, i4, d, N2 / 4);
    float4 gdf = grad_s(fixed4,  i4, d, N2 / 4);
    float4 ghw = grad_s(warped4, i4, h, N / 4);
    float4 ghf = grad_s(fixed4,  i4, h, N / 4);
    float4 gww = grad_w_shfl(wc, lane);
    float4 gwf = grad_w_shfl(fc, lane);

    float4 v0 = vf4[i4];
    float4 v1 = vf4[i4 + N3 / 4];
    float4 v2 = vf4[i4 + 2 * N3 / 4];

    float4 u0, u1, u2;
#pragma unroll
    for (int j = 0; j < 4; j++) {
        float diff = ((const float*)&wc)[j] - ((const float*)&fc)[j];
        float g0 = 0.5f * (((const float*)&gdw)[j] + ((const float*)&gdf)[j]);
        float g1 = 0.5f * (((const float*)&ghw)[j] + ((const float*)&ghf)[j]);
        float g2 = 0.5f * (((const float*)&gww)[j] + ((const float*)&gwf)[j]);
        float denom = g0 * g0 + g1 * g1 + g2 * g2 + diff * diff;
        float s = (denom > 1e-6f) ? (diff / denom) : 0.0f;
        ((float*)&u0)[j] = ((const float*)&v0)[j] + s * g0;
        ((float*)&u1)[j] = ((const float*)&v1)[j] + s * g1;
        ((float*)&u2)[j] = ((const float*)&v2)[j] + s * g2;
    }

    // Fused W-axis smoothing (applies first; separable passes commute)
    u4[i4]              = wsmooth_shfl(u0, lane);
    u4[i4 + N3 / 4]     = wsmooth_shfl(u1, lane);
    u4[i4 + 2 * N3 / 4] = wsmooth_shfl(u2, lane);
}

// ---------------------------------------------------------------------------
// Strided-axis 7-tap Gaussian, 4 outputs per thread along the axis.
// Layout: [outer][axis=128][INNER float4s]. Taps c0-3 .. c0+6 -> 10 loads
// per 4 float4 outputs (2.5 loads/output instead of 7).
// D axis: INNER = N2/4 (outer = 3 channels). H axis: INNER = N/4 (outer = 3*128).
// ---------------------------------------------------------------------------
template <int INNER>
__global__ void smooth_s4_kernel(const float4* __restrict__ in4,
                                 float4* __restrict__ out4) {
    int t = blockIdx.x * blockDim.x + threadIdx.x;    // over 3*N3/16
    if (t >= 3 * N3 / 16) return;
    int inner = t % INNER;
    int cb    = (t / INNER) & 31;
    int outer = t / (INNER * 32);
    int c0 = cb * 4;

    const float4* p = in4 + (size_t)outer * (128 * INNER) + inner;

    float4 tap[10];
#pragma unroll
    for (int j = 0; j < 10; j++) {
        int c = c0 + j - 3;
        if (c >= 0 && c < 128) tap[j] = p[c * INNER];
        else                   tap[j] = make_float4(0.f, 0.f, 0.f, 0.f);
    }

    float4* q = out4 + (size_t)outer * (128 * INNER) + inner;
#pragma unroll
    for (int j = 0; j < 4; j++) {
        float4 acc;
        acc.x = GW[0] * tap[3 + j].x;
        acc.y = GW[0] * tap[3 + j].y;
        acc.z = GW[0] * tap[3 + j].z;
        acc.w = GW[0] * tap[3 + j].w;
#pragma unroll
        for (int s = 1; s <= 3; s++) {
            float4 a = tap[3 + j - s], b = tap[3 + j + s];
            acc.x += GW[s] * (a.x + b.x);
            acc.y += GW[s] * (a.y + b.y);
            acc.z += GW[s] * (a.z + b.z);
            acc.w += GW[s] * (a.w + b.w);
        }
        q[(c0 + j) * INNER] = acc;
    }
}

extern "C" void kernel_launch(void* const* d_in, const int* in_sizes, int n_in,
                              void* d_out, int out_size) {
    const float* moving = (const float*)d_in[0];
    const float4* fixed4 = (const float4*)d_in[1];
    float4* vf4 = (float4*)d_out;

    float *warped_p, *u_p, *t_p;
    cudaGetSymbolAddress((void**)&warped_p, g_warped);
    cudaGetSymbolAddress((void**)&u_p, g_u);
    cudaGetSymbolAddress((void**)&t_p, g_t);
    float4* warped4 = (float4*)warped_p;
    float4* u4 = (float4*)u_p;
    float4* t4 = (float4*)t_p;

    const int T = 256;
    const int B1 = (N3 / 4) / T;            // 2048
    const int B3 = (3 * N3 / 4) / T;        // 6144
    const int BS = (3 * N3 / 16) / T;       // 1536

    zero_kernel<<<B3, T>>>(vf4);

    for (int it = 0; it < 20; it++) {
        warp_kernel<<<B1, T>>>(moving, vf4, warped4);
        force_w_kernel<<<B1, T>>>(warped4, fixed4, vf4, u4);   // force + W smooth
        smooth_s4_kernel<N2 / 4><<<BS, T>>>(u4, t4);           // D axis
        smooth_s4_kernel<N / 4><<<BS, T>>>(t4, vf4);           // H axis
    }
}